// round 1
// baseline (speedup 1.0000x reference)
#include <cuda_runtime.h>

#define W_IMG 1024
#define H_IMG 1024
#define C_IMG 3
#define N_IMG 16

__global__ __launch_bounds__(256) void homography_warp_kernel(
    const float* __restrict__ img,    // [N, C, H, W]
    const float* __restrict__ homo,   // [N, 3, 3]
    float* __restrict__ out)          // [N, C, H, W]
{
    const int n   = blockIdx.y;
    const int idx = blockIdx.x * 256 + threadIdx.x;   // pixel index within image
    const int w   = idx & (W_IMG - 1);
    const int h   = idx >> 10;

    // Broadcast this image's 3x3 homography through shared memory.
    __shared__ float Hm[9];
    if (threadIdx.x < 9) Hm[threadIdx.x] = homo[n * 9 + threadIdx.x];
    __syncthreads();

    // Normalized grid coords in [-1, 1] (align_corners=True semantics).
    const float gx = (float)w * (2.0f / 1023.0f) - 1.0f;
    const float gy = (float)h * (2.0f / 1023.0f) - 1.0f;

    // Homogeneous transform.
    const float X = Hm[0] * gx + Hm[1] * gy + Hm[2];
    const float Y = Hm[3] * gx + Hm[4] * gy + Hm[5];
    const float Z = Hm[6] * gx + Hm[7] * gy + Hm[8];
    const float inv = 1.0f / Z;

    // Back to pixel coords.
    const float x = (X * inv + 1.0f) * (0.5f * (float)(W_IMG - 1));
    const float y = (Y * inv + 1.0f) * (0.5f * (float)(H_IMG - 1));

    const float x0f = floorf(x);
    const float y0f = floorf(y);
    const int x0 = (int)x0f;
    const int y0 = (int)y0f;
    const int x1 = x0 + 1;
    const int y1 = y0 + 1;

    const float wx1 = x - x0f;
    const float wx0 = 1.0f - wx1;
    const float wy1 = y - y0f;
    const float wy0 = 1.0f - wy1;

    // zeros-padding validity per corner (matches reference: mask, clip for gather).
    const bool vx0 = (x0 >= 0) & (x0 < W_IMG);
    const bool vx1 = (x1 >= 0) & (x1 < W_IMG);
    const bool vy0 = (y0 >= 0) & (y0 < H_IMG);
    const bool vy1 = (y1 >= 0) & (y1 < H_IMG);

    const int x0c = min(max(x0, 0), W_IMG - 1);
    const int x1c = min(max(x1, 0), W_IMG - 1);
    const int y0c = min(max(y0, 0), H_IMG - 1);
    const int y1c = min(max(y1, 0), H_IMG - 1);

    const float w00 = (vx0 && vy0) ? (wx0 * wy0) : 0.0f;
    const float w01 = (vx1 && vy0) ? (wx1 * wy0) : 0.0f;
    const float w10 = (vx0 && vy1) ? (wx0 * wy1) : 0.0f;
    const float w11 = (vx1 && vy1) ? (wx1 * wy1) : 0.0f;

    const size_t plane = (size_t)H_IMG * W_IMG;
    const float* base = img + (size_t)n * C_IMG * plane;
    const size_t r0 = (size_t)y0c * W_IMG;
    const size_t r1 = (size_t)y1c * W_IMG;

    float* outp = out + (size_t)n * C_IMG * plane + (size_t)h * W_IMG + w;

#pragma unroll
    for (int c = 0; c < C_IMG; c++) {
        const float* p = base + (size_t)c * plane;
        const float v = __ldg(p + r0 + x0c) * w00
                      + __ldg(p + r0 + x1c) * w01
                      + __ldg(p + r1 + x0c) * w10
                      + __ldg(p + r1 + x1c) * w11;
        outp[c * plane] = v;
    }
}

extern "C" void kernel_launch(void* const* d_in, const int* in_sizes, int n_in,
                              void* d_out, int out_size) {
    const float* patch_src    = (const float*)d_in[0];  // [16,3,1024,1024]
    const float* dst_homo_src = (const float*)d_in[1];  // [16,3,3]
    float* out = (float*)d_out;

    dim3 grid((H_IMG * W_IMG) / 256, N_IMG);
    homography_warp_kernel<<<grid, 256>>>(patch_src, dst_homo_src, out);
}

// round 2
// speedup vs baseline: 1.0277x; 1.0277x over previous
#include <cuda_runtime.h>

#define W_IMG 1024
#define H_IMG 1024
#define C_IMG 3
#define N_IMG 16
#define PLANE (H_IMG * W_IMG)   // 1048576 elements per channel plane

__global__ __launch_bounds__(256) void homography_warp_kernel(
    const float* __restrict__ img,    // [N, C, H, W]
    const float* __restrict__ homo,   // [N, 3, 3]
    float* __restrict__ out)          // [N, C, H, W]
{
    const int n   = blockIdx.y;
    const int idx = blockIdx.x * 256 + threadIdx.x;   // pixel index within image
    const int w   = idx & (W_IMG - 1);
    const int h   = idx >> 10;

    // Broadcast this image's 3x3 homography through shared memory.
    __shared__ float Hm[9];
    if (threadIdx.x < 9) Hm[threadIdx.x] = homo[n * 9 + threadIdx.x];
    __syncthreads();

    // Normalized grid coords in [-1, 1] (align_corners=True semantics).
    const float gx = (float)w * (2.0f / 1023.0f) - 1.0f;
    const float gy = (float)h * (2.0f / 1023.0f) - 1.0f;

    // Homogeneous transform.
    const float X = Hm[0] * gx + Hm[1] * gy + Hm[2];
    const float Y = Hm[3] * gx + Hm[4] * gy + Hm[5];
    const float Z = Hm[6] * gx + Hm[7] * gy + Hm[8];
    const float inv = 1.0f / Z;

    // Back to pixel coords.
    const float x = (X * inv + 1.0f) * (0.5f * (float)(W_IMG - 1));
    const float y = (Y * inv + 1.0f) * (0.5f * (float)(H_IMG - 1));

    const float x0f = floorf(x);
    const float y0f = floorf(y);
    const int x0 = (int)x0f;
    const int y0 = (int)y0f;

    const float wx1 = x - x0f;
    const float wx0 = 1.0f - wx1;
    const float wy1 = y - y0f;
    const float wy0 = 1.0f - wy1;

    // Base pointers anchored at CHANNEL 1 so channel offsets are -PLANE, 0, +PLANE
    // (byte offsets +-4MB fit in the LDG/STG immediate field).
    const float* pc1 = img + n * (C_IMG * PLANE) + PLANE;
    float*       oc1 = out + n * (C_IMG * PLANE) + PLANE + (idx);

    const bool interior = (x0 >= 0) & (x0 <= W_IMG - 2) & (y0 >= 0) & (y0 <= H_IMG - 2);

    if (__all_sync(0xFFFFFFFFu, interior)) {
        // ---- fast path: all 4 corners in-bounds for every lane in the warp ----
        const float w00 = wx0 * wy0;
        const float w01 = wx1 * wy0;
        const float w10 = wx0 * wy1;
        const float w11 = wx1 * wy1;

        const float* q = pc1 + (y0 * W_IMG + x0);   // single gather base (channel 1, row0, x0)

#pragma unroll
        for (int c = -1; c <= 1; c++) {
            const int co = c * PLANE;
            const float v = q[co]              * w00
                          + q[co + 1]          * w01
                          + q[co + W_IMG]      * w10
                          + q[co + W_IMG + 1]  * w11;
            oc1[c * PLANE] = v;
        }
    } else {
        // ---- slow path: full masked/clamped zeros-padding semantics ----
        const int x1 = x0 + 1;
        const int y1 = y0 + 1;

        const bool vx0 = (x0 >= 0) & (x0 < W_IMG);
        const bool vx1 = (x1 >= 0) & (x1 < W_IMG);
        const bool vy0 = (y0 >= 0) & (y0 < H_IMG);
        const bool vy1 = (y1 >= 0) & (y1 < H_IMG);

        const int x0c = min(max(x0, 0), W_IMG - 1);
        const int x1c = min(max(x1, 0), W_IMG - 1);
        const int y0c = min(max(y0, 0), H_IMG - 1);
        const int y1c = min(max(y1, 0), H_IMG - 1);

        const float w00 = (vx0 && vy0) ? (wx0 * wy0) : 0.0f;
        const float w01 = (vx1 && vy0) ? (wx1 * wy0) : 0.0f;
        const float w10 = (vx0 && vy1) ? (wx0 * wy1) : 0.0f;
        const float w11 = (vx1 && vy1) ? (wx1 * wy1) : 0.0f;

        const int r0 = y0c * W_IMG;
        const int r1 = y1c * W_IMG;

#pragma unroll
        for (int c = -1; c <= 1; c++) {
            const int co = c * PLANE;
            const float v = pc1[co + r0 + x0c] * w00
                          + pc1[co + r0 + x1c] * w01
                          + pc1[co + r1 + x0c] * w10
                          + pc1[co + r1 + x1c] * w11;
            oc1[c * PLANE] = v;
        }
    }
}

extern "C" void kernel_launch(void* const* d_in, const int* in_sizes, int n_in,
                              void* d_out, int out_size) {
    const float* patch_src    = (const float*)d_in[0];  // [16,3,1024,1024]
    const float* dst_homo_src = (const float*)d_in[1];  // [16,3,3]
    float* out = (float*)d_out;

    dim3 grid((H_IMG * W_IMG) / 256, N_IMG);
    homography_warp_kernel<<<grid, 256>>>(patch_src, dst_homo_src, out);
}